// round 5
// baseline (speedup 1.0000x reference)
#include <cuda_runtime.h>
#include <math.h>

// Problem constants
#define Bc   128
#define Tc   600
#define Uc   96
#define Kc   10
#define CDc  80
#define Sc   512
#define OUTD 121
#define KT1  595     // cell1 fused K: 3 + 80 + 512
#define KT2  1107    // cell2/3 fused K: 3 + 512 + 80 + 512
#define NBLK 148
#define NTHR 256

// ---------------- persistent device state (static, no allocations) -------------
__device__ __align__(16) float g_Wf1[KT1 * 1024];  // interleaved j/k columns
__device__ __align__(16) float g_Wf2[KT2 * 1024];
__device__ __align__(16) float g_bf1[1024];
__device__ __align__(16) float g_bf2[1024];
__device__ __align__(16) float g_h1[2][Bc * Sc];
__device__ __align__(16) float g_h2[2][Bc * Sc];
__device__ __align__(16) float g_h3[2][Bc * Sc];
__device__ float g_kappa[Bc * Kc];
__device__ float g_w[Bc * CDc];
__device__ __align__(16) float g_ys[(size_t)Bc * Tc * Sc];   // [b*T + t][S]
__device__ unsigned g_bar_cnt;
__device__ volatile unsigned g_bar_gen;

// Shared memory union: GEMM tiles / attention scratch / k-split reduction
union SharedU {
    struct { float Ws[4][32][64]; float As[4][16][36]; } g;
    struct { float h[Sc]; float part[30][8]; float abk[32]; float phi[Uc]; } a;
    float red[3 * 64 * 20];
};

// ---------------- grid-wide barrier (all NBLK blocks resident) ------------------
__device__ __forceinline__ void grid_bar()
{
    __threadfence();          // flush this thread's global writes toward L2
    __syncthreads();
    if (threadIdx.x == 0) {
        unsigned gen = g_bar_gen;
        if (atomicAdd(&g_bar_cnt, 1) == NBLK - 1) {
            g_bar_cnt = 0;
            __threadfence();
            g_bar_gen = gen + 1;
        } else {
            while (g_bar_gen == gen) { }
        }
    }
    __syncthreads();
}

// ---------------- prep: fuse weights, combine biases, zero state ----------------
__global__ void prep_kernel(
    const float* __restrict__ Wjx1, const float* __restrict__ bjx1,
    const float* __restrict__ Wjh1, const float* __restrict__ bjh1,
    const float* __restrict__ Wkx1, const float* __restrict__ bkx1,
    const float* __restrict__ Wkh1, const float* __restrict__ bkh1,
    const float* __restrict__ Wjx2, const float* __restrict__ bjx2,
    const float* __restrict__ Wjh2, const float* __restrict__ bjh2,
    const float* __restrict__ Wkx2, const float* __restrict__ bkx2,
    const float* __restrict__ Wkh2, const float* __restrict__ bkh2)
{
    const int stride = gridDim.x * blockDim.x;
    const int t0 = blockIdx.x * blockDim.x + threadIdx.x;

    if (t0 == 0) { g_bar_cnt = 0; g_bar_gen = 0; }

    for (int idx = t0; idx < KT1 * 1024; idx += stride) {
        int d = idx >> 10, c = idx & 1023;
        int s = c >> 1, isk = c & 1;
        float v;
        if (d < 83) v = isk ? Wkx1[d * Sc + s] : Wjx1[d * Sc + s];
        else        v = isk ? Wkh1[(d - 83) * Sc + s] : Wjh1[(d - 83) * Sc + s];
        g_Wf1[idx] = v;
    }
    for (int idx = t0; idx < KT2 * 1024; idx += stride) {
        int d = idx >> 10, c = idx & 1023;
        int s = c >> 1, isk = c & 1;
        float v;
        if (d < 595) v = isk ? Wkx2[d * Sc + s] : Wjx2[d * Sc + s];
        else         v = isk ? Wkh2[(d - 595) * Sc + s] : Wjh2[(d - 595) * Sc + s];
        g_Wf2[idx] = v;
    }
    for (int idx = t0; idx < 1024; idx += stride) {
        int s = idx >> 1, isk = idx & 1;
        g_bf1[idx] = isk ? (bkx1[s] + bkh1[s]) : (bjx1[s] + bjh1[s]);
        g_bf2[idx] = isk ? (bkx2[s] + bkh2[s]) : (bjx2[s] + bjh2[s]);
    }
    for (int idx = t0; idx < Bc * Sc; idx += stride) {
        g_h1[0][idx] = 0.f; g_h2[0][idx] = 0.f; g_h3[0][idx] = 0.f;
    }
    for (int idx = t0; idx < Bc * CDc; idx += stride) g_w[idx] = 0.f;
    for (int idx = t0; idx < Bc * Kc; idx += stride) g_kappa[idx] = 0.f;
}

// ---------------- gated-cell GEMM phase (inside persistent kernel) --------------
// 128 working blocks; block = 16b x 64c tile; 4 k-groups x 64 threads; 4b x 4c.
template <int CELL>
__device__ void cell_phase(SharedU& sh, const float* __restrict__ x, int t, int pi)
{
    constexpr int KT  = (CELL == 1) ? KT1 : KT2;
    constexpr int NIT = ((KT + 31) / 32 + 3) / 4;   // 5 or 9

    const int bid = blockIdx.x;
    if (bid >= 128) return;

    const int po = pi ^ 1;
    const float* __restrict__ Wf    = (CELL == 1) ? g_Wf1 : g_Wf2;
    const float* __restrict__ bf    = (CELL == 1) ? g_bf1 : g_bf2;
    const float* __restrict__ h_old = (CELL == 1) ? g_h1[pi] : (CELL == 2) ? g_h2[pi] : g_h3[pi];
    float* __restrict__       h_new = (CELL == 1) ? g_h1[po] : (CELL == 2) ? g_h2[po] : g_h3[po];
    const float* __restrict__ hin   = (CELL == 2) ? g_h1[po] : g_h2[po];  // unused for CELL==1

    const int tid  = threadIdx.x;
    const int kg   = tid >> 6;      // k-group 0..3
    const int lt   = tid & 63;
    const int tb   = lt >> 4;       // 0..3 -> 4 rows each
    const int tcq  = lt & 15;       // 0..15 -> 4 cols each
    const int warp = lt >> 5;       // 0..1 within group
    const int lane = lt & 31;
    const int c0 = (bid & 15) * 64;
    const int b0 = (bid >> 4) * 16;

    float4 acc[4];
    {
        float4 bv = (kg == 0) ? *(const float4*)&bf[c0 + tcq * 4]
                              : make_float4(0.f, 0.f, 0.f, 0.f);
        acc[0] = bv; acc[1] = bv; acc[2] = bv; acc[3] = bv;
    }

    for (int it = 0; it < NIT; ++it) {
        const int k0 = (it * 4 + kg) * 32;

        // weight tile: 32 k-rows x 64 cols, 8 float4 per thread
#pragma unroll
        for (int i = 0; i < 8; ++i) {
            int idx = lt + i * 64;
            int r = idx >> 4, q = idx & 15;
            int kr = k0 + r;
            float4 v = make_float4(0.f, 0.f, 0.f, 0.f);
            if (kr < KT) v = *(const float4*)&Wf[(size_t)kr * 1024 + c0 + q * 4];
            *(float4*)&sh.g.Ws[kg][r][q * 4] = v;
        }
        // activation tile: 16 b x 32 k; warp-coalesced gather, transposed store
#pragma unroll
        for (int i = 0; i < 8; ++i) {
            int bb = warp * 8 + i;
            int b = b0 + bb;
            int k = k0 + lane;
            float v = 0.f;
            if (k < KT) {
                if (CELL == 1) {
                    if (k < 3)       v = x[b * (Tc * 3) + t * 3 + k];
                    else if (k < 83) v = __ldcg(&g_w[b * CDc + (k - 3)]);
                    else             v = __ldcg(&h_old[b * Sc + (k - 83)]);
                } else {
                    if (k < 3)        v = x[b * (Tc * 3) + t * 3 + k];
                    else if (k < 515) v = __ldcg(&hin[b * Sc + (k - 3)]);
                    else if (k < 595) v = __ldcg(&g_w[b * CDc + (k - 515)]);
                    else              v = __ldcg(&h_old[b * Sc + (k - 595)]);
                }
            }
            sh.g.As[kg][bb][lane] = v;
        }
        __syncthreads();

#pragma unroll
        for (int kq = 0; kq < 8; ++kq) {
            float4 a0 = *(const float4*)&sh.g.As[kg][tb * 4 + 0][kq * 4];
            float4 a1 = *(const float4*)&sh.g.As[kg][tb * 4 + 1][kq * 4];
            float4 a2 = *(const float4*)&sh.g.As[kg][tb * 4 + 2][kq * 4];
            float4 a3 = *(const float4*)&sh.g.As[kg][tb * 4 + 3][kq * 4];
            float4 w0 = *(const float4*)&sh.g.Ws[kg][kq * 4 + 0][tcq * 4];
            float4 w1 = *(const float4*)&sh.g.Ws[kg][kq * 4 + 1][tcq * 4];
            float4 w2 = *(const float4*)&sh.g.Ws[kg][kq * 4 + 2][tcq * 4];
            float4 w3 = *(const float4*)&sh.g.Ws[kg][kq * 4 + 3][tcq * 4];
#define FMA4(A, S, W) { (A).x += (S)*(W).x; (A).y += (S)*(W).y; (A).z += (S)*(W).z; (A).w += (S)*(W).w; }
            FMA4(acc[0], a0.x, w0); FMA4(acc[1], a1.x, w0); FMA4(acc[2], a2.x, w0); FMA4(acc[3], a3.x, w0);
            FMA4(acc[0], a0.y, w1); FMA4(acc[1], a1.y, w1); FMA4(acc[2], a2.y, w1); FMA4(acc[3], a3.y, w1);
            FMA4(acc[0], a0.z, w2); FMA4(acc[1], a1.z, w2); FMA4(acc[2], a2.z, w2); FMA4(acc[3], a3.z, w2);
            FMA4(acc[0], a0.w, w3); FMA4(acc[1], a1.w, w3); FMA4(acc[2], a2.w, w3); FMA4(acc[3], a3.w, w3);
#undef FMA4
        }
        __syncthreads();
    }

    // ---- k-split reduction: groups 1..3 dump, group 0 accumulates ----
    if (kg > 0) {
        float* r = sh.red + (size_t)((kg - 1) * 64 + lt) * 20;
        *(float4*)(r + 0)  = acc[0];
        *(float4*)(r + 4)  = acc[1];
        *(float4*)(r + 8)  = acc[2];
        *(float4*)(r + 12) = acc[3];
    }
    __syncthreads();
    if (kg == 0) {
#pragma unroll
        for (int g2 = 0; g2 < 3; ++g2) {
            const float* r = sh.red + (size_t)(g2 * 64 + lt) * 20;
#pragma unroll
            for (int i = 0; i < 4; ++i) {
                float4 v = *(const float4*)(r + i * 4);
                acc[i].x += v.x; acc[i].y += v.y; acc[i].z += v.z; acc[i].w += v.w;
            }
        }
        // ---- epilogue: gate combine (even col = j, odd col = k) ----
#pragma unroll
        for (int i = 0; i < 4; ++i) {
            int b = b0 + tb * 4 + i;
#pragma unroll
            for (int p = 0; p < 2; ++p) {
                int c = c0 + tcq * 4 + 2 * p;
                int s = c >> 1;
                float pj = (p == 0) ? acc[i].x : acc[i].z;
                float pk = (p == 0) ? acc[i].y : acc[i].w;
                float jv = 1.f / (1.f + expf(-pj));
                float kv = 1.f / (1.f + expf(-pk));
                float h = h_old[b * Sc + s];      // written by this block last step
                float hn = jv * (1.f - h) + (1.f - kv) * h;
                h_new[b * Sc + s] = hn;
                if (CELL == 3) g_ys[((size_t)b * Tc + t) * Sc + s] = hn;
            }
        }
    }
    __syncthreads();
}

// ---------------- attention window phase (block b handles batch b) --------------
__device__ void attn_phase(SharedU& sh,
                           const float* __restrict__ c_vec,
                           const float* __restrict__ W_win,
                           const float* __restrict__ b_win, int pi)
{
    const int b = blockIdx.x;
    if (b >= Bc) return;
    const int tid = threadIdx.x;
    const float* __restrict__ h1 = g_h1[pi ^ 1];

    for (int i = tid; i < Sc; i += NTHR) sh.a.h[i] = __ldcg(&h1[b * Sc + i]);
    __syncthreads();

    if (tid < 240) {
        int c = tid >> 3, p = tid & 7;
        float s = 0.f;
        int d0 = p * 64;
#pragma unroll 4
        for (int d = d0; d < d0 + 64; ++d) s += sh.a.h[d] * W_win[d * 30 + c];
        sh.a.part[c][p] = s;
    }
    __syncthreads();

    if (tid < 30) {
        float v = b_win[tid];
#pragma unroll
        for (int p = 0; p < 8; ++p) v += sh.a.part[tid][p];
        float e = expf(v);
        if (tid >= 20) {
            int i = b * Kc + (tid - 20);
            float kn = g_kappa[i] + e;
            g_kappa[i] = kn;           // only this block touches batch b
            sh.a.abk[tid] = kn;
        } else {
            sh.a.abk[tid] = e;
        }
    }
    __syncthreads();

    if (tid < Uc) {
        float u = (float)tid;
        float phi = 0.f;
#pragma unroll
        for (int k = 0; k < Kc; ++k) {
            float d = sh.a.abk[20 + k] - u;
            phi += sh.a.abk[k] * expf(-sh.a.abk[10 + k] * d * d);
        }
        sh.a.phi[tid] = phi;
    }
    __syncthreads();

    if (tid < CDc) {
        float acc = 0.f;
        const float* cv = c_vec + (size_t)b * Uc * CDc + tid;
#pragma unroll 4
        for (int u = 0; u < Uc; ++u) acc += sh.a.phi[u] * cv[u * CDc];
        g_w[b * CDc + tid] = acc;
    }
    __syncthreads();
}

// ---------------- persistent RNN kernel -----------------------------------------
__global__ __launch_bounds__(NTHR, 1) void rnn_kernel(
    const float* __restrict__ x, const float* __restrict__ c_vec,
    const float* __restrict__ W_win, const float* __restrict__ b_win)
{
    __shared__ SharedU sh;

    for (int t = 0; t < Tc; ++t) {
        int pi = t & 1;
        cell_phase<1>(sh, x, t, pi);
        grid_bar();
        attn_phase(sh, c_vec, W_win, b_win, pi);
        grid_bar();
        cell_phase<2>(sh, x, t, pi);
        grid_bar();
        cell_phase<3>(sh, x, t, pi);
        grid_bar();
    }
}

// ---------------- final projection: out = ys @ W_lin + b_lin --------------------
__global__ __launch_bounds__(256) void final_kernel(
    const float* __restrict__ W_lin, const float* __restrict__ b_lin,
    float* __restrict__ out)
{
    __shared__ __align__(16) float As[16][68];
    __shared__ __align__(16) float Ws[16][128];

    const int tid = threadIdx.x;
    const int tcx = tid & 31;      // 0..31 -> 4 cols
    const int tr  = tid >> 5;      // 0..7  -> 8 rows
    const int r0 = blockIdx.x * 64;

    float acc[8][4];
#pragma unroll
    for (int i = 0; i < 8; i++)
#pragma unroll
        for (int j = 0; j < 4; j++) acc[i][j] = 0.f;

    for (int k0 = 0; k0 < Sc; k0 += 16) {
        {
            int r = tid >> 2, q = tid & 3;
            float4 v = *(const float4*)(g_ys + (size_t)(r0 + r) * Sc + k0 + q * 4);
            As[q * 4 + 0][r] = v.x; As[q * 4 + 1][r] = v.y;
            As[q * 4 + 2][r] = v.z; As[q * 4 + 3][r] = v.w;
        }
#pragma unroll
        for (int i = 0; i < 8; i++) {
            int idx = tid + i * 256;
            int r = idx >> 7, c = idx & 127;
            Ws[r][c] = (c < OUTD) ? W_lin[(k0 + r) * OUTD + c] : 0.f;
        }
        __syncthreads();
#pragma unroll
        for (int kk = 0; kk < 16; kk++) {
            float4 a0 = *(const float4*)(&As[kk][tr * 8]);
            float4 a1 = *(const float4*)(&As[kk][tr * 8 + 4]);
            float4 w  = *(const float4*)(&Ws[kk][tcx * 4]);
            float av[8] = {a0.x, a0.y, a0.z, a0.w, a1.x, a1.y, a1.z, a1.w};
#pragma unroll
            for (int i = 0; i < 8; i++) {
                acc[i][0] += av[i] * w.x; acc[i][1] += av[i] * w.y;
                acc[i][2] += av[i] * w.z; acc[i][3] += av[i] * w.w;
            }
        }
        __syncthreads();
    }

#pragma unroll
    for (int i = 0; i < 8; i++) {
        int row = r0 + tr * 8 + i;
#pragma unroll
        for (int j = 0; j < 4; j++) {
            int c = tcx * 4 + j;
            if (c < OUTD) out[(size_t)row * OUTD + c] = acc[i][j] + b_lin[c];
        }
    }
}

// ---------------- launch --------------------------------------------------------
extern "C" void kernel_launch(void* const* d_in, const int* in_sizes, int n_in,
                              void* d_out, int out_size)
{
    const float* x     = (const float*)d_in[0];
    const float* c_vec = (const float*)d_in[1];
    const float* W_win = (const float*)d_in[18];
    const float* b_win = (const float*)d_in[19];
    const float* W_lin = (const float*)d_in[20];
    const float* b_lin = (const float*)d_in[21];

    prep_kernel<<<512, 256>>>(
        (const float*)d_in[2],  (const float*)d_in[3],
        (const float*)d_in[4],  (const float*)d_in[5],
        (const float*)d_in[6],  (const float*)d_in[7],
        (const float*)d_in[8],  (const float*)d_in[9],
        (const float*)d_in[10], (const float*)d_in[11],
        (const float*)d_in[12], (const float*)d_in[13],
        (const float*)d_in[14], (const float*)d_in[15],
        (const float*)d_in[16], (const float*)d_in[17]);

    rnn_kernel<<<NBLK, NTHR>>>(x, c_vec, W_win, b_win);

    final_kernel<<<(Bc * Tc) / 64, 256>>>(W_lin, b_lin, (float*)d_out);
}

// round 9
// speedup vs baseline: 1.5668x; 1.5668x over previous
#include <cuda_runtime.h>
#include <math.h>

// Problem constants
#define Bc   128
#define Tc   600
#define Uc   96
#define Kc   10
#define CDc  80
#define Sc   512
#define OUTD 121
#define KT1  595     // cell1 fused K: 3 + 80 + 512
#define KT2  1107    // cell2/3 fused K: 3 + 512 + 80 + 512
#define NBLK 128
#define NTHR 256

typedef unsigned long long ull;

// ---------------- packed f32x2 helpers ------------------------------------------
#define FMA2(D, A, W) asm("fma.rn.f32x2 %0, %1, %2, %0;" : "+l"(D) : "l"(A), "l"(W))
#define ADD2(D, S)    asm("add.rn.f32x2 %0, %0, %1;"     : "+l"(D) : "l"(S))

// ---------------- persistent device state (static, no allocations) --------------
__device__ __align__(16) float g_Wf1[KT1 * 1024];  // interleaved j/k columns
__device__ __align__(16) float g_Wf2[KT2 * 1024];
__device__ __align__(16) float g_bf1[1024];
__device__ __align__(16) float g_bf2[1024];
__device__ __align__(16) float g_h1[2][Bc * Sc];
__device__ __align__(16) float g_h2[2][Bc * Sc];
__device__ __align__(16) float g_h3[2][Bc * Sc];
__device__ float g_kappa[Bc * Kc];
__device__ float g_w[Bc * CDc];
__device__ float g_kgpart[16][Bc][30];             // per-ctile window-head partials
__device__ __align__(16) float g_ys[(size_t)Bc * Tc * Sc];
__device__ unsigned g_cnt[8];
__device__ unsigned g_root;
__device__ volatile unsigned g_gen;

// Shared memory union
union SharedU {
    struct { float Ws[4][32][64]; float As2[4][32][34]; } g;   // 50176 B
    struct { float red[3][64][16]; float htile[16][33]; } r;   // 14400 B
    struct { float abk[32]; float phi[Uc]; } a;
};
#define SMEM_BYTES ((int)sizeof(SharedU))

// ---------------- two-level grid barrier (128 blocks, monotonic) ----------------
__device__ __forceinline__ void grid_bar(unsigned nbar)
{
    __threadfence();
    __syncthreads();
    if (threadIdx.x == 0) {
        unsigned g = blockIdx.x & 7;
        unsigned v = atomicAdd(&g_cnt[g], 1) + 1;
        if (v == nbar * 16u) {                       // 16 blocks per sub-counter
            unsigned r = atomicAdd(&g_root, 1) + 1;
            if (r == nbar * 8u) {
                __threadfence();
                g_gen = nbar;
            }
        }
        int sp = 0;
        while (g_gen < nbar) { if (++sp > 8) __nanosleep(64); }
    }
    __syncthreads();
}

// ---------------- prep: fuse weights, combine biases, zero state ----------------
__global__ void prep_kernel(
    const float* __restrict__ Wjx1, const float* __restrict__ bjx1,
    const float* __restrict__ Wjh1, const float* __restrict__ bjh1,
    const float* __restrict__ Wkx1, const float* __restrict__ bkx1,
    const float* __restrict__ Wkh1, const float* __restrict__ bkh1,
    const float* __restrict__ Wjx2, const float* __restrict__ bjx2,
    const float* __restrict__ Wjh2, const float* __restrict__ bjh2,
    const float* __restrict__ Wkx2, const float* __restrict__ bkx2,
    const float* __restrict__ Wkh2, const float* __restrict__ bkh2)
{
    const int stride = gridDim.x * blockDim.x;
    const int t0 = blockIdx.x * blockDim.x + threadIdx.x;

    if (t0 == 0) {
        for (int i = 0; i < 8; i++) g_cnt[i] = 0;
        g_root = 0; g_gen = 0;
    }

    for (int idx = t0; idx < KT1 * 1024; idx += stride) {
        int d = idx >> 10, c = idx & 1023;
        int s = c >> 1, isk = c & 1;
        float v;
        if (d < 83) v = isk ? Wkx1[d * Sc + s] : Wjx1[d * Sc + s];
        else        v = isk ? Wkh1[(d - 83) * Sc + s] : Wjh1[(d - 83) * Sc + s];
        g_Wf1[idx] = v;
    }
    for (int idx = t0; idx < KT2 * 1024; idx += stride) {
        int d = idx >> 10, c = idx & 1023;
        int s = c >> 1, isk = c & 1;
        float v;
        if (d < 595) v = isk ? Wkx2[d * Sc + s] : Wjx2[d * Sc + s];
        else         v = isk ? Wkh2[(d - 595) * Sc + s] : Wjh2[(d - 595) * Sc + s];
        g_Wf2[idx] = v;
    }
    for (int idx = t0; idx < 1024; idx += stride) {
        int s = idx >> 1, isk = idx & 1;
        g_bf1[idx] = isk ? (bkx1[s] + bkh1[s]) : (bjx1[s] + bjh1[s]);
        g_bf2[idx] = isk ? (bkx2[s] + bkh2[s]) : (bjx2[s] + bjh2[s]);
    }
    for (int idx = t0; idx < Bc * Sc; idx += stride) {
        g_h1[0][idx] = 0.f; g_h1[1][idx] = 0.f;
        g_h2[0][idx] = 0.f; g_h2[1][idx] = 0.f;
        g_h3[0][idx] = 0.f; g_h3[1][idx] = 0.f;
    }
    for (int idx = t0; idx < Bc * CDc; idx += stride) g_w[idx] = 0.f;
    for (int idx = t0; idx < Bc * Kc; idx += stride) g_kappa[idx] = 0.f;
}

// ---------------- gated-cell GEMM phase (f32x2, reg-prefetch pipelined) ---------
// 128 blocks; tile 16b x 64c; 4 k-groups x 64 threads; thread tile 4b x (2x f32x2).
template <int CELL>
__device__ void cell_phase(SharedU& sh, const float* __restrict__ x,
                           const float* __restrict__ W_win, int t)
{
    constexpr int KT  = (CELL == 1) ? KT1 : KT2;
    constexpr int NIT = (KT + 127) / 128;          // 5 or 9

    const int pi = t & 1;
    const float* __restrict__ Wf    = (CELL == 1) ? g_Wf1 : g_Wf2;
    const float* __restrict__ bf    = (CELL == 1) ? g_bf1 : g_bf2;
    const float* __restrict__ h_old = (CELL == 1) ? g_h1[pi ^ 1]
                                   : (CELL == 2) ? g_h2[pi ^ 1] : g_h3[pi ^ 1];
    float* __restrict__       h_new = (CELL == 1) ? g_h1[pi]
                                   : (CELL == 2) ? g_h2[pi] : g_h3[pi];
    const float* __restrict__ hin   = (CELL == 2) ? g_h1[pi] : g_h2[pi];

    const int tid  = threadIdx.x;
    const int kg   = tid >> 6;
    const int lt   = tid & 63;
    const int tb   = lt >> 4;       // 0..3 -> 4 b each
    const int tcq  = lt & 15;       // 0..15 -> cols tcq*4..+3 (2 f32x2 pairs)
    const int w2   = lt >> 5;
    const int lane = lt & 31;
    const int bid  = blockIdx.x;
    const int c0 = (bid & 15) * 64;
    const int b0 = (bid >> 4) * 16;

    ull acc[4][2];
    {
        ull blo = 0, bhi = 0;
        if (kg == 0) {
            blo = *(const ull*)&bf[c0 + tcq * 4];
            bhi = *(const ull*)&bf[c0 + tcq * 4 + 2];
        }
#pragma unroll
        for (int i = 0; i < 4; i++) { acc[i][0] = blo; acc[i][1] = bhi; }
    }

    float4 wpre[8];
    float  apre[8];

    auto gatherA = [&](int k, int b) -> float {
        if (k >= KT) return 0.f;
        if (CELL == 1) {
            if (k < 3)  return x[b * (Tc * 3) + t * 3 + k];
            if (k < 83) return __ldcg(&g_w[b * CDc + (k - 3)]);
            return __ldcg(&h_old[b * Sc + (k - 83)]);
        } else {
            if (k < 3)   return x[b * (Tc * 3) + t * 3 + k];
            if (k < 515) return __ldcg(&hin[b * Sc + (k - 3)]);
            if (k < 595) return __ldcg(&g_w[b * CDc + (k - 515)]);
            return __ldcg(&h_old[b * Sc + (k - 595)]);
        }
    };
    auto loadRegs = [&](int it) {
        const int k0g = (it * 4 + kg) * 32;
#pragma unroll
        for (int i = 0; i < 8; i++) {
            int idx = lt + i * 64;
            int r = idx >> 4, q = idx & 15;
            int kr = k0g + r;
            wpre[i] = (kr < KT) ? *(const float4*)&Wf[(size_t)kr * 1024 + c0 + q * 4]
                                : make_float4(0.f, 0.f, 0.f, 0.f);
        }
#pragma unroll
        for (int i = 0; i < 8; i++)
            apre[i] = gatherA(k0g + lane, b0 + w2 * 8 + i);
    };
    auto storeRegs = [&]() {
#pragma unroll
        for (int i = 0; i < 8; i++) {
            int idx = lt + i * 64;
            int r = idx >> 4, q = idx & 15;
            *(float4*)&sh.g.Ws[kg][r][q * 4] = wpre[i];
        }
#pragma unroll
        for (int i = 0; i < 8; i++) {
            int col = 2 * (w2 * 8 + i);
            *(float2*)&sh.g.As2[kg][lane][col] = make_float2(apre[i], apre[i]);
        }
    };

    loadRegs(0); storeRegs(); __syncthreads();

    for (int it = 0; it < NIT; ++it) {
        if (it + 1 < NIT) loadRegs(it + 1);   // global loads overlap compute below
#pragma unroll
        for (int k = 0; k < 32; ++k) {
            const float* ar = &sh.g.As2[kg][k][tb * 8];
            ull a0 = *(const ull*)(ar + 0);
            ull a1 = *(const ull*)(ar + 2);
            ull a2 = *(const ull*)(ar + 4);
            ull a3 = *(const ull*)(ar + 6);
            const float* wr = &sh.g.Ws[kg][k][tcq * 4];
            ull w0 = *(const ull*)(wr + 0);
            ull w1 = *(const ull*)(wr + 2);
            FMA2(acc[0][0], a0, w0); FMA2(acc[0][1], a0, w1);
            FMA2(acc[1][0], a1, w0); FMA2(acc[1][1], a1, w1);
            FMA2(acc[2][0], a2, w0); FMA2(acc[2][1], a2, w1);
            FMA2(acc[3][0], a3, w0); FMA2(acc[3][1], a3, w1);
        }
        __syncthreads();
        if (it + 1 < NIT) { storeRegs(); __syncthreads(); }
    }

    // ---- k-split reduction ----
    __syncthreads();
    if (kg > 0) {
        ull* r = (ull*)&sh.r.red[kg - 1][lt][0];
#pragma unroll
        for (int i = 0; i < 4; i++) { r[i * 2] = acc[i][0]; r[i * 2 + 1] = acc[i][1]; }
    }
    __syncthreads();
    if (kg == 0) {
#pragma unroll
        for (int g2 = 0; g2 < 3; ++g2) {
            const ull* r = (const ull*)&sh.r.red[g2][lt][0];
#pragma unroll
            for (int i = 0; i < 4; i++) { ADD2(acc[i][0], r[i * 2]); ADD2(acc[i][1], r[i * 2 + 1]); }
        }
        // ---- epilogue: each f32x2 pair = (preact_j, preact_k) for one s ----
#pragma unroll
        for (int i = 0; i < 4; i++) {
            int b = b0 + tb * 4 + i;
#pragma unroll
            for (int p = 0; p < 2; p++) {
                float pj, pk;
                asm("mov.b64 {%0,%1}, %2;" : "=f"(pj), "=f"(pk) : "l"(acc[i][p]));
                int s = (c0 + tcq * 4 + 2 * p) >> 1;
                float jv = 1.f / (1.f + __expf(-pj));
                float kv = 1.f / (1.f + __expf(-pk));
                float h = h_old[b * Sc + s];
                float hn = jv * (1.f - h) + (1.f - kv) * h;
                h_new[b * Sc + s] = hn;
                if (CELL == 3) g_ys[((size_t)b * Tc + t) * Sc + s] = hn;
                if (CELL == 1) sh.r.htile[tb * 4 + i][tcq * 2 + p] = hn;
            }
        }
    }

    // ---- cell1 only: window-head partials kgpart[ct][b][30] over this 32-s slice
    if (CELL == 1) {
        __syncthreads();
        if (tid < 240) {
            int bb = tid / 15, cp = tid % 15;
            int c  = cp * 2;
            int ct = bid & 15;
            int s0 = ct * 32;
            float a0 = 0.f, a1 = 0.f;
#pragma unroll 4
            for (int s2 = 0; s2 < 32; ++s2) {
                float hv = sh.r.htile[bb][s2];
                a0 += hv * W_win[(s0 + s2) * 30 + c];
                a1 += hv * W_win[(s0 + s2) * 30 + c + 1];
            }
            g_kgpart[ct][b0 + bb][c]     = a0;
            g_kgpart[ct][b0 + bb][c + 1] = a1;
        }
    }
    __syncthreads();
}

// ---------------- attention window phase (block b = batch b) --------------------
__device__ void attn_phase(SharedU& sh, const float* __restrict__ c_vec,
                           const float* __restrict__ b_win)
{
    const int b = blockIdx.x;
    const int tid = threadIdx.x;

    if (tid < 30) {
        float v = b_win[tid];
#pragma unroll
        for (int ct = 0; ct < 16; ++ct) v += __ldcg(&g_kgpart[ct][b][tid]);
        float e = __expf(v);
        if (tid >= 20) {
            int i = b * Kc + (tid - 20);
            float kn = g_kappa[i] + e;     // only this block touches batch b
            g_kappa[i] = kn;
            sh.a.abk[tid] = kn;
        } else {
            sh.a.abk[tid] = e;
        }
    }
    __syncthreads();

    if (tid < Uc) {
        float u = (float)tid;
        float phi = 0.f;
#pragma unroll
        for (int k = 0; k < Kc; ++k) {
            float d = sh.a.abk[20 + k] - u;
            phi += sh.a.abk[k] * __expf(-sh.a.abk[10 + k] * d * d);
        }
        sh.a.phi[tid] = phi;
    }
    __syncthreads();

    if (tid < CDc) {
        float acc = 0.f;
        const float* cv = c_vec + (size_t)b * Uc * CDc + tid;
#pragma unroll 4
        for (int u = 0; u < Uc; ++u) acc += sh.a.phi[u] * __ldg(&cv[u * CDc]);
        g_w[b * CDc + tid] = acc;
    }
    __syncthreads();
}

// ---------------- persistent RNN kernel -----------------------------------------
__global__ __launch_bounds__(NTHR, 1) void rnn_kernel(
    const float* __restrict__ x, const float* __restrict__ c_vec,
    const float* __restrict__ W_win, const float* __restrict__ b_win)
{
    extern __shared__ SharedU sh_ext[];
    SharedU& sh = sh_ext[0];
    unsigned nbar = 0;

    // prime: cell1(0) + window-head partials
    cell_phase<1>(sh, x, W_win, 0);
    grid_bar(++nbar);

    for (int t = 0; t < Tc; ++t) {
        attn_phase(sh, c_vec, b_win);            // w(t)
        grid_bar(++nbar);
        cell_phase<2>(sh, x, W_win, t);          // h2(t)
        grid_bar(++nbar);
        cell_phase<3>(sh, x, W_win, t);          // h3(t), ys
        if (t + 1 < Tc) cell_phase<1>(sh, x, W_win, t + 1);  // h1(t+1), kgpart
        grid_bar(++nbar);
    }
}

// ---------------- final projection: out = ys @ W_lin + b_lin --------------------
__global__ __launch_bounds__(256) void final_kernel(
    const float* __restrict__ W_lin, const float* __restrict__ b_lin,
    float* __restrict__ out)
{
    __shared__ __align__(16) float As[16][68];
    __shared__ __align__(16) float Ws[16][128];

    const int tid = threadIdx.x;
    const int tcx = tid & 31;
    const int tr  = tid >> 5;
    const int r0 = blockIdx.x * 64;

    float acc[8][4];
#pragma unroll
    for (int i = 0; i < 8; i++)
#pragma unroll
        for (int j = 0; j < 4; j++) acc[i][j] = 0.f;

    for (int k0 = 0; k0 < Sc; k0 += 16) {
        {
            int r = tid >> 2, q = tid & 3;
            float4 v = *(const float4*)(g_ys + (size_t)(r0 + r) * Sc + k0 + q * 4);
            As[q * 4 + 0][r] = v.x; As[q * 4 + 1][r] = v.y;
            As[q * 4 + 2][r] = v.z; As[q * 4 + 3][r] = v.w;
        }
#pragma unroll
        for (int i = 0; i < 8; i++) {
            int idx = tid + i * 256;
            int r = idx >> 7, c = idx & 127;
            Ws[r][c] = (c < OUTD) ? W_lin[(k0 + r) * OUTD + c] : 0.f;
        }
        __syncthreads();
#pragma unroll
        for (int kk = 0; kk < 16; kk++) {
            float4 a0 = *(const float4*)(&As[kk][tr * 8]);
            float4 a1 = *(const float4*)(&As[kk][tr * 8 + 4]);
            float4 w  = *(const float4*)(&Ws[kk][tcx * 4]);
            float av[8] = {a0.x, a0.y, a0.z, a0.w, a1.x, a1.y, a1.z, a1.w};
#pragma unroll
            for (int i = 0; i < 8; i++) {
                acc[i][0] += av[i] * w.x; acc[i][1] += av[i] * w.y;
                acc[i][2] += av[i] * w.z; acc[i][3] += av[i] * w.w;
            }
        }
        __syncthreads();
    }

#pragma unroll
    for (int i = 0; i < 8; i++) {
        int row = r0 + tr * 8 + i;
#pragma unroll
        for (int j = 0; j < 4; j++) {
            int c = tcx * 4 + j;
            if (c < OUTD) out[(size_t)row * OUTD + c] = acc[i][j] + b_lin[c];
        }
    }
}

// ---------------- launch --------------------------------------------------------
extern "C" void kernel_launch(void* const* d_in, const int* in_sizes, int n_in,
                              void* d_out, int out_size)
{
    const float* x     = (const float*)d_in[0];
    const float* c_vec = (const float*)d_in[1];
    const float* W_win = (const float*)d_in[18];
    const float* b_win = (const float*)d_in[19];
    const float* W_lin = (const float*)d_in[20];
    const float* b_lin = (const float*)d_in[21];

    cudaFuncSetAttribute(rnn_kernel, cudaFuncAttributeMaxDynamicSharedMemorySize,
                         SMEM_BYTES);

    prep_kernel<<<512, 256>>>(
        (const float*)d_in[2],  (const float*)d_in[3],
        (const float*)d_in[4],  (const float*)d_in[5],
        (const float*)d_in[6],  (const float*)d_in[7],
        (const float*)d_in[8],  (const float*)d_in[9],
        (const float*)d_in[10], (const float*)d_in[11],
        (const float*)d_in[12], (const float*)d_in[13],
        (const float*)d_in[14], (const float*)d_in[15],
        (const float*)d_in[16], (const float*)d_in[17]);

    rnn_kernel<<<NBLK, NTHR, SMEM_BYTES>>>(x, c_vec, W_win, b_win);

    final_kernel<<<(Bc * Tc) / 64, 256>>>(W_lin, b_lin, (float*)d_out);
}